// round 1
// baseline (speedup 1.0000x reference)
#include <cuda_runtime.h>
#include <math.h>

#define BATCH 2
#define SEQ   8192
#define DIM   512
#define BM    32
#define BN    64

// scratch for projected K, Q, V (allocation-free rule: __device__ globals)
__device__ float g_K[BATCH * SEQ * DIM];
__device__ float g_Q[BATCH * SEQ * DIM];
__device__ float g_V[BATCH * SEQ * DIM];

// ---------------------------------------------------------------------------
// Projection GEMM: C[M][N] = X[M][K] @ W[N][K]^T + b   (M=16384, N=K=512)
// 64x64 tile, 256 threads, 4x4 micro-tile, k-chunks of 16.
// ---------------------------------------------------------------------------
__global__ __launch_bounds__(256) void proj_kernel(
    const float* __restrict__ X, const float* __restrict__ W,
    const float* __restrict__ bias, float* __restrict__ C)
{
    __shared__ float xs[16][68];   // [kk][m], pad 68 keeps float4 alignment
    __shared__ float ws[16][68];   // [kk][n]

    const int tx = threadIdx.x & 15;
    const int ty = threadIdx.x >> 4;
    const int m0 = blockIdx.y * 64;
    const int n0 = blockIdx.x * 64;
    const int lk = threadIdx.x & 15;   // k within chunk
    const int lr = threadIdx.x >> 4;   // row base

    float acc[4][4] = {};

    for (int k0 = 0; k0 < DIM; k0 += 16) {
        #pragma unroll
        for (int i = 0; i < 4; i++) {
            int r = lr + i * 16;
            xs[lk][r] = X[(size_t)(m0 + r) * DIM + k0 + lk];
            ws[lk][r] = W[(size_t)(n0 + r) * DIM + k0 + lk];
        }
        __syncthreads();
        #pragma unroll
        for (int kk = 0; kk < 16; kk++) {
            float4 xv = *(const float4*)&xs[kk][ty * 4];
            float4 wv = *(const float4*)&ws[kk][tx * 4];
            float xr[4] = {xv.x, xv.y, xv.z, xv.w};
            float wr[4] = {wv.x, wv.y, wv.z, wv.w};
            #pragma unroll
            for (int r = 0; r < 4; r++)
                #pragma unroll
                for (int c = 0; c < 4; c++)
                    acc[r][c] += xr[r] * wr[c];
        }
        __syncthreads();
    }

    float4 bv = *(const float4*)&bias[n0 + tx * 4];
    float br[4] = {bv.x, bv.y, bv.z, bv.w};
    #pragma unroll
    for (int r = 0; r < 4; r++) {
        float4 ov;
        ov.x = acc[r][0] + br[0];
        ov.y = acc[r][1] + br[1];
        ov.z = acc[r][2] + br[2];
        ov.w = acc[r][3] + br[3];
        *(float4*)&C[(size_t)(m0 + ty * 4 + r) * DIM + n0 + tx * 4] = ov;
    }
}

// ---------------------------------------------------------------------------
// Flash attention (fp32, online softmax).
// rows (s) come from K, cols (t) from Q;  out[s] = sum_t softmax(k_s . q_t) v_t
// Block: 32 rows x full D.  256 threads = 16(ty: 2 rows each) x 16(tx: 4 cols).
// ---------------------------------------------------------------------------
__global__ __launch_bounds__(256, 2) void attn_kernel(float* __restrict__ out)
{
    extern __shared__ float sm[];
    float* ks = sm;                     // [BM][DIM]          16384 f
    float* qs = sm + BM * DIM;          // [32][68] d-major    2176 f
    float* vs = qs + 32 * 68;           // [64][64]            4096 f
    float* ps = vs + 64 * 64;           // [32][68]            2176 f

    const int b  = blockIdx.y;
    const int m0 = blockIdx.x * BM;
    const float* Kp = g_K + (size_t)b * SEQ * DIM;
    const float* Qp = g_Q + (size_t)b * SEQ * DIM;
    const float* Vp = g_V + (size_t)b * SEQ * DIM;

    const int tid = threadIdx.x;
    const int tx  = tid & 15;
    const int ty  = tid >> 4;

    // K tile -> shared (reused across all 128 column tiles)
    {
        const float4* src = (const float4*)(Kp + (size_t)m0 * DIM);
        float4* dst = (float4*)ks;
        #pragma unroll
        for (int i = tid; i < BM * DIM / 4; i += 256) dst[i] = src[i];
    }
    __syncthreads();

    float o[2][8][4];
    #pragma unroll
    for (int r = 0; r < 2; r++)
        #pragma unroll
        for (int dc = 0; dc < 8; dc++)
            #pragma unroll
            for (int c = 0; c < 4; c++) o[r][dc][c] = 0.f;

    float mrow[2] = {-INFINITY, -INFINITY};
    float lrow[2] = {0.f, 0.f};

    const int qk = tid & 31;   // d within 32-chunk (Q load)
    const int qn = tid >> 5;   // col base        (Q load)
    const int vn = tid >> 4;   // row base        (V load)
    const int vd = (tid & 15) * 4;

    for (int n0 = 0; n0 < SEQ; n0 += BN) {
        // ---- Phase A: S = K_tile @ Q_tile^T (32x64 in regs) ----
        float s[2][4] = {};
        for (int d0 = 0; d0 < DIM; d0 += 32) {
            #pragma unroll
            for (int i = 0; i < 8; i++) {
                int n = qn + 8 * i;
                qs[qk * 68 + n] = Qp[(size_t)(n0 + n) * DIM + d0 + qk];
            }
            __syncthreads();
            #pragma unroll
            for (int kk = 0; kk < 32; kk++) {
                float4 qv = *(const float4*)&qs[kk * 68 + tx * 4];
                float k0v = ks[(2 * ty)     * DIM + d0 + kk];
                float k1v = ks[(2 * ty + 1) * DIM + d0 + kk];
                s[0][0] += k0v * qv.x; s[0][1] += k0v * qv.y;
                s[0][2] += k0v * qv.z; s[0][3] += k0v * qv.w;
                s[1][0] += k1v * qv.x; s[1][1] += k1v * qv.y;
                s[1][2] += k1v * qv.z; s[1][3] += k1v * qv.w;
            }
            __syncthreads();
        }

        // ---- Phase B: online softmax update ----
        #pragma unroll
        for (int r = 0; r < 2; r++) {
            float mx = fmaxf(fmaxf(s[r][0], s[r][1]), fmaxf(s[r][2], s[r][3]));
            #pragma unroll
            for (int off = 1; off < 16; off <<= 1)
                mx = fmaxf(mx, __shfl_xor_sync(0xffffffffu, mx, off));
            float mnew = fmaxf(mrow[r], mx);
            if (mnew > mrow[r]) {
                float scale = __expf(mrow[r] - mnew);   // exp(-inf)=0 first time
                lrow[r] *= scale;
                #pragma unroll
                for (int dc = 0; dc < 8; dc++)
                    #pragma unroll
                    for (int c = 0; c < 4; c++) o[r][dc][c] *= scale;
                mrow[r] = mnew;
            }
            float p[4], rs = 0.f;
            #pragma unroll
            for (int c = 0; c < 4; c++) {
                p[c] = __expf(s[r][c] - mrow[r]);
                rs += p[c];
            }
            #pragma unroll
            for (int off = 1; off < 16; off <<= 1)
                rs += __shfl_xor_sync(0xffffffffu, rs, off);
            lrow[r] += rs;
            #pragma unroll
            for (int c = 0; c < 4; c++)
                ps[(2 * ty + r) * 68 + tx * 4 + c] = p[c];
        }
        __syncthreads();

        // ---- Phase C: O += P @ V (stream V in 64-wide d-chunks) ----
        #pragma unroll 1
        for (int dc = 0; dc < 8; dc++) {
            int d0 = dc * 64;
            #pragma unroll
            for (int i = 0; i < 4; i++) {
                int n = vn + 16 * i;
                *(float4*)&vs[n * 64 + vd] =
                    *(const float4*)&Vp[(size_t)(n0 + n) * DIM + d0 + vd];
            }
            __syncthreads();
            #pragma unroll 8
            for (int n = 0; n < 64; n++) {
                float4 vv = *(const float4*)&vs[n * 64 + tx * 4];
                float p0 = ps[(2 * ty)     * 68 + n];
                float p1 = ps[(2 * ty + 1) * 68 + n];
                o[0][dc][0] += p0 * vv.x; o[0][dc][1] += p0 * vv.y;
                o[0][dc][2] += p0 * vv.z; o[0][dc][3] += p0 * vv.w;
                o[1][dc][0] += p1 * vv.x; o[1][dc][1] += p1 * vv.y;
                o[1][dc][2] += p1 * vv.z; o[1][dc][3] += p1 * vv.w;
            }
            __syncthreads();
        }
    }

    // ---- epilogue: out = O / l ----
    #pragma unroll
    for (int r = 0; r < 2; r++) {
        float inv = 1.f / lrow[r];
        size_t row = (size_t)(b * SEQ + m0 + 2 * ty + r) * DIM;
        #pragma unroll
        for (int dc = 0; dc < 8; dc++) {
            float4 ov;
            ov.x = o[r][dc][0] * inv;
            ov.y = o[r][dc][1] * inv;
            ov.z = o[r][dc][2] * inv;
            ov.w = o[r][dc][3] * inv;
            *(float4*)&out[row + dc * 64 + tx * 4] = ov;
        }
    }
}

__global__ void mask_kernel(float* __restrict__ p)
{
    p[threadIdx.x] = 0.f;
}

// ---------------------------------------------------------------------------
extern "C" void kernel_launch(void* const* d_in, const int* in_sizes, int n_in,
                              void* d_out, int out_size)
{
    (void)in_sizes; (void)n_in; (void)out_size;
    const float* x  = (const float*)d_in[0];
    const float* Wk = (const float*)d_in[1];
    const float* bk = (const float*)d_in[2];
    const float* Wq = (const float*)d_in[3];
    const float* bq = (const float*)d_in[4];
    const float* Wv = (const float*)d_in[5];
    const float* bv = (const float*)d_in[6];
    float* out = (float*)d_out;

    float *Kb, *Qb, *Vb;
    cudaGetSymbolAddress((void**)&Kb, g_K);
    cudaGetSymbolAddress((void**)&Qb, g_Q);
    cudaGetSymbolAddress((void**)&Vb, g_V);

    dim3 pgrid(DIM / 64, (BATCH * SEQ) / 64);
    proj_kernel<<<pgrid, 256>>>(x, Wk, bk, Kb);
    proj_kernel<<<pgrid, 256>>>(x, Wq, bq, Qb);
    proj_kernel<<<pgrid, 256>>>(x, Wv, bv, Vb);

    size_t smem = (size_t)(BM * DIM + 32 * 68 + 64 * 64 + 32 * 68) * sizeof(float);
    cudaFuncSetAttribute(attn_kernel, cudaFuncAttributeMaxDynamicSharedMemorySize,
                         (int)smem);
    attn_kernel<<<dim3(SEQ / BM, BATCH), 256, smem>>>(out);

    mask_kernel<<<1, 16>>>(out + (size_t)BATCH * SEQ * DIM);
}